// round 2
// baseline (speedup 1.0000x reference)
#include <cuda_runtime.h>
#include <math.h>

// Problem constants
#define BB 2
#define TT 1024
#define CC 1024
#define HH 16
#define LL 4
#define VV 50257
#define DD 64
#define FF 4096

// ---------------- scratch (device globals: allocation-guard safe) ----------
__device__ float g_x [BB*TT*CC];   // residual stream
__device__ float g_h [BB*TT*CC];   // LN output
__device__ float g_q [BB*TT*CC];
__device__ float g_k [BB*TT*CC];
__device__ float g_v [BB*TT*CC];
__device__ float g_y [BB*TT*CC];   // attention output
__device__ float g_h2[BB*TT*FF];   // MLP hidden

// ---------------- embedding -------------------------------------------------
__global__ void embed_kernel(const int* __restrict__ idx,
                             const float* __restrict__ tok,
                             const float* __restrict__ pos,
                             float* __restrict__ x) {
    int i = blockIdx.x * blockDim.x + threadIdx.x;
    if (i < BB*TT*CC) {
        int c  = i % CC;
        int bt = i / CC;
        int t  = bt % TT;
        x[i] = tok[(size_t)idx[bt] * CC + c] + pos[(size_t)t * CC + c];
    }
}

// ---------------- layernorm (one block per row of C=1024) ------------------
__global__ void ln_kernel(const float* __restrict__ in,
                          float* __restrict__ out,
                          const float* __restrict__ w,
                          const float* __restrict__ b) {
    int row = blockIdx.x;
    const float* xr = in + (size_t)row * CC;
    __shared__ float red[256];
    int tid = threadIdx.x;

    float s = 0.f;
    for (int i = tid; i < CC; i += 256) s += xr[i];
    red[tid] = s; __syncthreads();
    for (int o = 128; o > 0; o >>= 1) {
        if (tid < o) red[tid] += red[tid + o];
        __syncthreads();
    }
    float mu = red[0] * (1.0f / CC);
    __syncthreads();

    float vs = 0.f;
    for (int i = tid; i < CC; i += 256) { float d = xr[i] - mu; vs += d * d; }
    red[tid] = vs; __syncthreads();
    for (int o = 128; o > 0; o >>= 1) {
        if (tid < o) red[tid] += red[tid + o];
        __syncthreads();
    }
    float rstd = rsqrtf(red[0] * (1.0f / CC) + 1e-5f);

    for (int i = tid; i < CC; i += 256)
        out[(size_t)row * CC + i] = (xr[i] - mu) * rstd * w[i] + b[i];
}

// ---------------- NT GEMM: C[m,n] = sum_k A[m,k]*B[n,k] (+bias +resid, act) -
// A: [M,K] row-major, B: [N,K] row-major. 64x64 tile, BK=16, 4x4 per thread.
template<bool BIAS, bool RES, bool GELU_>
__global__ void __launch_bounds__(256)
gemm_nt(const float* __restrict__ A, const float* __restrict__ Bm,
        const float* __restrict__ bias, const float* __restrict__ resid,
        float* __restrict__ Cm, int M, int N, int K) {
    __shared__ float As[16][64];
    __shared__ float Bs[16][64];

    int tid = threadIdx.x;
    int tr = tid >> 4;          // 0..15
    int tc = tid & 15;          // 0..15
    int m0 = blockIdx.y * 64;
    int n0 = blockIdx.x * 64;

    int a_m = tid >> 2;               // 0..63
    int a_k = (tid & 3) << 2;         // 0,4,8,12

    float acc[4][4];
    #pragma unroll
    for (int i = 0; i < 4; i++)
        #pragma unroll
        for (int j = 0; j < 4; j++) acc[i][j] = 0.f;

    for (int kt = 0; kt < K; kt += 16) {
        // load A tile (M always multiple of 64 here)
        float4 av = *(const float4*)(A + (size_t)(m0 + a_m) * K + kt + a_k);
        As[a_k + 0][a_m] = av.x;
        As[a_k + 1][a_m] = av.y;
        As[a_k + 2][a_m] = av.z;
        As[a_k + 3][a_m] = av.w;
        // load B tile (guard n for head GEMM where N=50257)
        int b_n = n0 + a_m;
        float4 bv = make_float4(0.f, 0.f, 0.f, 0.f);
        if (b_n < N)
            bv = *(const float4*)(Bm + (size_t)b_n * K + kt + a_k);
        Bs[a_k + 0][a_m] = bv.x;
        Bs[a_k + 1][a_m] = bv.y;
        Bs[a_k + 2][a_m] = bv.z;
        Bs[a_k + 3][a_m] = bv.w;
        __syncthreads();

        #pragma unroll
        for (int kk = 0; kk < 16; kk++) {
            float ar[4], br[4];
            #pragma unroll
            for (int i = 0; i < 4; i++) ar[i] = As[kk][tr * 4 + i];
            #pragma unroll
            for (int j = 0; j < 4; j++) br[j] = Bs[kk][tc * 4 + j];
            #pragma unroll
            for (int i = 0; i < 4; i++)
                #pragma unroll
                for (int j = 0; j < 4; j++)
                    acc[i][j] = fmaf(ar[i], br[j], acc[i][j]);
        }
        __syncthreads();
    }

    #pragma unroll
    for (int i = 0; i < 4; i++) {
        int m = m0 + tr * 4 + i;
        #pragma unroll
        for (int j = 0; j < 4; j++) {
            int n = n0 + tc * 4 + j;
            if (n < N) {
                float val = acc[i][j];
                if (BIAS) val += bias[n];
                if (RES)  val += resid[(size_t)m * N + n];
                if (GELU_) val = 0.5f * val * (1.0f + erff(val * 0.70710678118654752f));
                Cm[(size_t)m * N + n] = val;
            }
        }
    }
}

// ---------------- attention: one block per (q-row, b*h) --------------------
__global__ void __launch_bounds__(128)
attn_kernel(const float* __restrict__ q, const float* __restrict__ k,
            const float* __restrict__ v, float* __restrict__ y) {
    int qpos = blockIdx.x;
    int bh = blockIdx.y;
    int b = bh / HH;
    int h = bh % HH;
    int tid = threadIdx.x;

    __shared__ float qs[DD];
    __shared__ float sc[TT];
    __shared__ float red[128];
    __shared__ float yacc[2][DD];

    const float* qp = q + ((size_t)(b * TT + qpos)) * CC + h * DD;
    if (tid < DD) qs[tid] = qp[tid];
    __syncthreads();

    int len = qpos + 1;
    const float scale = 0.125f;  // 1/sqrt(64)

    float mx = -1e30f;
    for (int j = tid; j < len; j += 128) {
        const float* kp = k + ((size_t)(b * TT + j)) * CC + h * DD;
        float dot = 0.f;
        #pragma unroll
        for (int d = 0; d < DD; d += 4) {
            float4 k4 = *(const float4*)(kp + d);
            dot = fmaf(qs[d + 0], k4.x, dot);
            dot = fmaf(qs[d + 1], k4.y, dot);
            dot = fmaf(qs[d + 2], k4.z, dot);
            dot = fmaf(qs[d + 3], k4.w, dot);
        }
        float s = dot * scale;
        sc[j] = s;
        mx = fmaxf(mx, s);
    }
    red[tid] = mx; __syncthreads();
    for (int o = 64; o > 0; o >>= 1) {
        if (tid < o) red[tid] = fmaxf(red[tid], red[tid + o]);
        __syncthreads();
    }
    mx = red[0];
    __syncthreads();

    float sum = 0.f;
    for (int j = tid; j < len; j += 128) {
        float e = __expf(sc[j] - mx);
        sc[j] = e;
        sum += e;
    }
    red[tid] = sum; __syncthreads();
    for (int o = 64; o > 0; o >>= 1) {
        if (tid < o) red[tid] += red[tid + o];
        __syncthreads();
    }
    float inv = 1.0f / red[0];
    __syncthreads();

    int g = tid >> 6;     // 0..1
    int d = tid & 63;
    float acc = 0.f;
    for (int j = g; j < len; j += 2)
        acc = fmaf(sc[j], v[((size_t)(b * TT + j)) * CC + h * DD + d], acc);
    yacc[g][d] = acc;
    __syncthreads();
    if (tid < DD)
        y[((size_t)(b * TT + qpos)) * CC + h * DD + tid] =
            (yacc[0][tid] + yacc[1][tid]) * inv;
}

// ---------------- host orchestration ---------------------------------------
static inline dim3 gemm_grid(int M, int N) {
    return dim3((N + 63) / 64, (M + 63) / 64);
}

extern "C" void kernel_launch(void* const* d_in, const int* in_sizes, int n_in,
                              void* d_out, int out_size) {
    const int*   idx    = (const int*)  d_in[0];
    const float* tok    = (const float*)d_in[1];
    const float* pos    = (const float*)d_in[2];
    const float* ln1w   = (const float*)d_in[3];
    const float* ln1b   = (const float*)d_in[4];
    const float* Wq     = (const float*)d_in[5];
    const float* bq     = (const float*)d_in[6];
    const float* Wk     = (const float*)d_in[7];
    const float* bk     = (const float*)d_in[8];
    const float* Wv     = (const float*)d_in[9];
    const float* bv     = (const float*)d_in[10];
    const float* Wo     = (const float*)d_in[11];
    const float* bo     = (const float*)d_in[12];
    const float* ln2w   = (const float*)d_in[13];
    const float* ln2b   = (const float*)d_in[14];
    const float* W1     = (const float*)d_in[15];
    const float* b1     = (const float*)d_in[16];
    const float* W2     = (const float*)d_in[17];
    const float* b2     = (const float*)d_in[18];
    const float* lnfw   = (const float*)d_in[19];
    const float* lnfb   = (const float*)d_in[20];
    const float* head_w = (const float*)d_in[21];
    float* out = (float*)d_out;

    float *x, *h, *q, *k, *v, *y, *h2;
    cudaGetSymbolAddress((void**)&x,  g_x);
    cudaGetSymbolAddress((void**)&h,  g_h);
    cudaGetSymbolAddress((void**)&q,  g_q);
    cudaGetSymbolAddress((void**)&k,  g_k);
    cudaGetSymbolAddress((void**)&v,  g_v);
    cudaGetSymbolAddress((void**)&y,  g_y);
    cudaGetSymbolAddress((void**)&h2, g_h2);

    const int M = BB * TT;      // 2048

    embed_kernel<<<(BB*TT*CC + 255) / 256, 256>>>(idx, tok, pos, x);

    for (int l = 0; l < LL; l++) {
        const float* wq = Wq + (size_t)l * CC * CC;
        const float* wk = Wk + (size_t)l * CC * CC;
        const float* wv = Wv + (size_t)l * CC * CC;
        const float* wo = Wo + (size_t)l * CC * CC;
        const float* w1 = W1 + (size_t)l * FF * CC;
        const float* w2 = W2 + (size_t)l * CC * FF;

        // LN1
        ln_kernel<<<M, 256>>>(x, h, ln1w + (size_t)l * CC, ln1b + (size_t)l * CC);
        // QKV
        gemm_nt<true, false, false><<<gemm_grid(M, CC), 256>>>(h, wq, bq + (size_t)l * CC, nullptr, q, M, CC, CC);
        gemm_nt<true, false, false><<<gemm_grid(M, CC), 256>>>(h, wk, bk + (size_t)l * CC, nullptr, k, M, CC, CC);
        gemm_nt<true, false, false><<<gemm_grid(M, CC), 256>>>(h, wv, bv + (size_t)l * CC, nullptr, v, M, CC, CC);
        // attention
        attn_kernel<<<dim3(TT, BB * HH), 128>>>(q, k, v, y);
        // output projection + residual (in-place into x, element-wise safe)
        gemm_nt<true, true, false><<<gemm_grid(M, CC), 256>>>(y, wo, bo + (size_t)l * CC, x, x, M, CC, CC);
        // LN2
        ln_kernel<<<M, 256>>>(x, h, ln2w + (size_t)l * CC, ln2b + (size_t)l * CC);
        // MLP
        gemm_nt<true, false, true ><<<gemm_grid(M, FF), 256>>>(h, w1, b1 + (size_t)l * FF, nullptr, h2, M, FF, CC);
        gemm_nt<true, true, false><<<gemm_grid(M, CC), 256>>>(h2, w2, b2 + (size_t)l * CC, x, x, M, CC, FF);
    }

    // final LN + head
    ln_kernel<<<M, 256>>>(x, h, lnfw, lnfb);
    gemm_nt<false, false, false><<<gemm_grid(M, VV), 256>>>(h, head_w, nullptr, nullptr, out, M, VV, CC);
}